// round 8
// baseline (speedup 1.0000x reference)
#include <cuda_runtime.h>
#include <cstdint>
#include <cstddef>

#define B_  256
#define C_  4
#define N_  64
#define F_  256
#define OC_ 8
#define OF_ 256
#define KSPLIT 8

typedef unsigned long long ull;

// Scratch (no allocations allowed)
__device__ float g_z[B_ * 2 * C_ * F_];            // 2 MB : concat(h, x)
__device__ float g_w[B_ * N_];                     // softmax weights
__device__ float g_s2[B_ * N_];                    // raw neighbor logits
__device__ float g_part[KSPLIT * B_ * OC_ * OF_];  // 16 MB : split-K partials

__device__ __forceinline__ float sqrt_ap(float v) {
    float r; asm("sqrt.approx.f32 %0, %1;" : "=f"(r) : "f"(v)); return r;
}
__device__ __forceinline__ float rcp_ap(float v) {
    float r; asm("rcp.approx.f32 %0, %1;" : "=f"(r) : "f"(v)); return r;
}
__device__ __forceinline__ ull pack2f(float v) {
    ull r; asm("mov.b64 %0, {%1, %2};" : "=l"(r) : "f"(v), "f"(v)); return r;
}
__device__ __forceinline__ void ffma2(ull& d, ull a, ull b) {
    asm("fma.rn.f32x2 %0, %1, %2, %0;" : "+l"(d) : "l"(a), "l"(b));
}

// ---------------------------------------------------------------------------
// Kernel 1a: s2 logits. Grid 1024.
// ---------------------------------------------------------------------------
__global__ __launch_bounds__(256) void k1a_logits(
    const float* __restrict__ nb, const float* __restrict__ Wa2)
{
    __shared__ float ws2[256];
    const int b = blockIdx.x >> 2, quarter = blockIdx.x & 3;
    const int t = threadIdx.x;
    const int lane = t & 31, w = t >> 5;

    ws2[t] = Wa2[t] + Wa2[256 + t] + Wa2[512 + t] + Wa2[768 + t];
    __syncthreads();

    const float* nbb = nb + (size_t)b * 65536;
    #pragma unroll
    for (int j = 0; j < 2; j++) {
        const int n = quarter * 16 + w * 2 + j;
        const float4* np = (const float4*)(nbb + n * 1024);
        float acc = 0.f;
        #pragma unroll
        for (int it = 0; it < 8; it++) {
            float4 q = np[it * 32 + lane];
            int f = (it * 128 + lane * 4) & 255;
            acc += q.x * ws2[f] + q.y * ws2[f + 1] + q.z * ws2[f + 2] + q.w * ws2[f + 3];
        }
        #pragma unroll
        for (int o = 16; o > 0; o >>= 1) acc += __shfl_xor_sync(0xffffffffu, acc, o);
        if (lane == 0) g_s2[b * 64 + n] = acc;
    }
}

// ---------------------------------------------------------------------------
// Kernel 1b: s1 + softmax; copy x into z channels 4..7.
// ---------------------------------------------------------------------------
__global__ __launch_bounds__(256) void k1b_softmax(
    const float* __restrict__ x, const float* __restrict__ Wa1)
{
    __shared__ float red[8];
    const int b = blockIdx.x;
    const int t = threadIdx.x;
    const int lane = t & 31, w = t >> 5;

    float w1 = Wa1[t] + Wa1[256 + t] + Wa1[512 + t] + Wa1[768 + t];

    float xs = 0.f;
    #pragma unroll
    for (int c = 0; c < 4; c++) {
        float xv = x[(b * 4 + c) * 256 + t];
        g_z[b * 2048 + (4 + c) * 256 + t] = xv;
        xs += xv;
    }
    float p = xs * w1;
    #pragma unroll
    for (int o = 16; o > 0; o >>= 1) p += __shfl_xor_sync(0xffffffffu, p, o);
    if (lane == 0) red[w] = p;
    __syncthreads();

    if (w == 0) {
        float s1v = red[lane & 7];
        #pragma unroll
        for (int o = 4; o > 0; o >>= 1) s1v += __shfl_xor_sync(0xffffffffu, s1v, o);
        float l0 = s1v * g_s2[b * 64 + lane];
        float l1 = s1v * g_s2[b * 64 + lane + 32];
        float m = fmaxf(l0, l1);
        #pragma unroll
        for (int o = 16; o > 0; o >>= 1) m = fmaxf(m, __shfl_xor_sync(0xffffffffu, m, o));
        float e0 = __expf(l0 - m), e1 = __expf(l1 - m);
        float s = e0 + e1;
        #pragma unroll
        for (int o = 16; o > 0; o >>= 1) s += __shfl_xor_sync(0xffffffffu, s, o);
        float inv = 1.f / s;
        g_w[b * 64 + lane]      = e0 * inv;
        g_w[b * 64 + lane + 32] = e1 * inv;
    }
}

// ---------------------------------------------------------------------------
// Kernel 2: v + adj + h, sgnroot computed ONCE per element (smem a-tile).
// 512 thr, one block per (b,c). Two 128-col halves. Dynamic smem: a-tile
// 256x136 (pad: row +8, +4 per 64-col group => conflict-free phases).
// ---------------------------------------------------------------------------
#define ADJ_STRIDE 136
#define K2_DSMEM (256 * ADJ_STRIDE * 4)

__global__ __launch_bounds__(512) void k2_adj(
    const float* __restrict__ x, const float* __restrict__ nb,
    float* __restrict__ adj)
{
    extern __shared__ float adjsm[];           // [256][ADJ_STRIDE]
    __shared__ float xs[256], vs[256], us[128], ids[128];
    __shared__ float wsm[64];
    __shared__ float pd[16 * 128];
    __shared__ float vp[512];
    __shared__ float hp[512];

    const int bc = blockIdx.x, b = bc >> 2, c = bc & 3;
    const int t = threadIdx.x;

    if (t < 64) wsm[t] = g_w[b * 64 + t];
    if (t < 256) xs[t] = x[bc * 256 + t];
    __syncthreads();

    // v[f] = sum_n w[n]*neighbor[b,n,c,f]  (split n-range over 2 thread-halves)
    {
        const int f = t & 255, nh = t >> 8;
        const float* nbp = nb + ((size_t)b * 256 + c) * 256 + f;
        float acc = 0.f;
        #pragma unroll 8
        for (int n = nh * 32; n < nh * 32 + 32; n++) acc += wsm[n] * nbp[(size_t)n * 1024];
        vp[t] = acc;
    }
    __syncthreads();
    if (t < 256) vs[t] = vp[t] + vp[256 + t];
    __syncthreads();

    const int colg = t & 31, rq = t >> 5;     // 4 cols, 16-row stripe
    const int jloc0 = colg * 4;
    const int pj0 = jloc0 + ((jloc0 >> 6) << 2);
    float hacc = 0.f;

    for (int ch = 0; ch < 2; ch++) {
        const int jg0 = ch * 128 + jloc0;
        float xc[4], vc[4];
        #pragma unroll
        for (int j = 0; j < 4; j++) { xc[j] = xs[jg0 + j]; vc[j] = vs[jg0 + j]; }

        // pass 1: a values -> regs + smem; |a| partials for den
        float4 areg[16];
        float dp0 = 0.f, dp1 = 0.f, dp2 = 0.f, dp3 = 0.f;
        #pragma unroll 4
        for (int ii = 0; ii < 16; ii++) {
            const int i = rq * 16 + ii;
            const float xi = xs[i], vi = vs[i];
            float4 av;
            #pragma unroll
            for (int j = 0; j < 4; j++) {
                float tv = xi * vc[j] + xc[j] * vi;
                float s = sqrt_ap(fmaxf(fabsf(tv), 1e-8f));
                (&av.x)[j] = (tv != 0.f) ? copysignf(s, tv) : 0.f;
            }
            dp0 += fabsf(av.x); dp1 += fabsf(av.y); dp2 += fabsf(av.z); dp3 += fabsf(av.w);
            *(float4*)&adjsm[i * ADJ_STRIDE + pj0] = av;
            areg[ii] = av;
        }
        {
            float4 d4 = make_float4(dp0, dp1, dp2, dp3);
            *(float4*)&pd[rq * 128 + jloc0] = d4;
        }
        __syncthreads();

        if (t < 128) {
            float den = 0.f;
            #pragma unroll
            for (int r = 0; r < 16; r++) den += pd[r * 128 + t];
            float id = rcp_ap(den + 1e-7f);
            ids[t] = id;
            us[t] = xs[ch * 128 + t] * id;
        }
        __syncthreads();

        // pass 2: scaled adj from regs -> DRAM (streaming STG.128)
        {
            float ic0 = ids[jloc0], ic1 = ids[jloc0 + 1], ic2 = ids[jloc0 + 2], ic3 = ids[jloc0 + 3];
            float* ap = adj + (size_t)bc * 65536 + jg0;
            #pragma unroll 4
            for (int ii = 0; ii < 16; ii++) {
                const int i = rq * 16 + ii;
                float4 av = areg[ii];
                float4 o = make_float4(av.x * ic0, av.y * ic1, av.z * ic2, av.w * ic3);
                __stcs((float4*)(ap + (size_t)i * 256), o);
            }
        }

        // pass 3: h rows from the smem a-tile (h[i] += sum_j a[i][j]*us[j])
        {
            const int r3 = t >> 1, jh = t & 1;
            const float* arow = &adjsm[r3 * ADJ_STRIDE + jh * 68];
            const float* urow = &us[jh * 64];
            float hs = 0.f;
            #pragma unroll 4
            for (int q = 0; q < 16; q++) {
                float4 av = *(const float4*)(arow + q * 4);
                float4 uv = *(const float4*)(urow + q * 4);
                hs += av.x * uv.x + av.y * uv.y + av.z * uv.z + av.w * uv.w;
            }
            hp[t] = hs;
        }
        __syncthreads();
        if (t < 256) hacc += hp[t * 2] + hp[t * 2 + 1];
        __syncthreads();   // adjsm reused next half
    }
    if (t < 256) g_z[b * 2048 + c * 256 + t] = hacc;
}

// ---------------------------------------------------------------------------
// Kernel 3: split-K GEMM. grid (16,2,8), 128 thr, tile 128x128, per-thread
// m16 x n8, dup-B (acc pairs along m). 2.0 B/FFMA2-lane operand stream =
// crossbar floor == fma floor. Bd groups skewed 16B/2 groups for bank spread.
// ---------------------------------------------------------------------------
#define K3_BROW 288
#define K3_DSMEM ((2 * 16 * 128 + 2 * 16 * K3_BROW) * 4)   // 53248 B

__global__ __launch_bounds__(128) void k3_gemm(const float* __restrict__ W)
{
    extern __shared__ float sm3[];
    float* const Asb = sm3;                   // 2 x [16][128]
    float* const Bdb = sm3 + 2 * 16 * 128;    // 2 x [16][K3_BROW]

    const int t = threadIdx.x;
    const int bn = blockIdx.x * 128, bm = blockIdx.y * 128, ks = blockIdx.z;
    const int mt = t >> 4;                           // 0..7
    const int nt = t & 15;                           // 0..15
    const int aoff = mt * 16;
    const int boff = nt * 16 + (nt >> 1) * 4;
    const int gn = t >> 3;
    const int bso = gn * 16 + (gn >> 1) * 4 + (t & 7) * 2;

    const float* Ag = g_z + (size_t)(bm + t) * 2048 + ks * 256;
    const float* Bg = W + (size_t)(bn + t) * 2048 + ks * 256;

    float4 apf[4], bpf[4];
    #pragma unroll
    for (int i = 0; i < 4; i++) { apf[i] = *(const float4*)(Ag + 4 * i); bpf[i] = *(const float4*)(Bg + 4 * i); }

    ull acc[8][8];
    #pragma unroll
    for (int mp = 0; mp < 8; mp++)
        #pragma unroll
        for (int n = 0; n < 8; n++) acc[mp][n] = 0ull;

    int buf = 0;
    for (int ch = 0; ch < 16; ch++) {
        float* As = Asb + buf * 2048;
        float* Bd = Bdb + buf * 16 * K3_BROW;
        #pragma unroll
        for (int i = 0; i < 4; i++)
            #pragma unroll
            for (int j = 0; j < 4; j++) {
                As[(i * 4 + j) * 128 + t] = (&apf[i].x)[j];
                *(ull*)&Bd[(i * 4 + j) * K3_BROW + bso] = pack2f((&bpf[i].x)[j]);
            }
        __syncthreads();

        if (ch < 15) {
            const float* Ag2 = Ag + (ch + 1) * 16;
            const float* Bg2 = Bg + (ch + 1) * 16;
            #pragma unroll
            for (int i = 0; i < 4; i++) { apf[i] = *(const float4*)(Ag2 + 4 * i); bpf[i] = *(const float4*)(Bg2 + 4 * i); }
        }

        #pragma unroll 4
        for (int k = 0; k < 16; k++) {
            const ull* ar = (const ull*)&As[k * 128 + aoff];
            const ull* br = (const ull*)&Bd[k * K3_BROW + boff];
            ull a[8], bb[8];
            #pragma unroll
            for (int i = 0; i < 8; i++) { a[i] = ar[i]; bb[i] = br[i]; }
            #pragma unroll
            for (int mp = 0; mp < 8; mp++)
                #pragma unroll
                for (int n = 0; n < 8; n++)
                    ffma2(acc[mp][n], a[mp], bb[n]);
        }
        buf ^= 1;
        __syncthreads();
    }

    // store split-K partials: acc[mp][n] = (row 2mp, row 2mp+1)
    float* pp = g_part + (size_t)ks * 524288;
    #pragma unroll
    for (int mp = 0; mp < 8; mp++) {
        const int r0 = bm + mt * 16 + 2 * mp;
        float lo[8], hi[8];
        #pragma unroll
        for (int n = 0; n < 8; n++) {
            float2 v = *(float2*)&acc[mp][n];
            lo[n] = v.x; hi[n] = v.y;
        }
        float* p0 = pp + (size_t)r0 * 2048 + bn + nt * 8;
        *(float4*)p0       = make_float4(lo[0], lo[1], lo[2], lo[3]);
        *(float4*)(p0 + 4) = make_float4(lo[4], lo[5], lo[6], lo[7]);
        float* p1 = p0 + 2048;
        *(float4*)p1       = make_float4(hi[0], hi[1], hi[2], hi[3]);
        *(float4*)(p1 + 4) = make_float4(hi[4], hi[5], hi[6], hi[7]);
    }
}

// ---------------------------------------------------------------------------
// Kernel 4: sum 8 split-K partials into out.
// ---------------------------------------------------------------------------
__global__ __launch_bounds__(256) void k4_reduce(float* __restrict__ out)
{
    const int i = (blockIdx.x * 256 + threadIdx.x) * 4;
    float4 o = *(const float4*)(g_part + i);
    #pragma unroll
    for (int s = 1; s < KSPLIT; s++) {
        const float4 p = *(const float4*)(g_part + (size_t)s * 524288 + i);
        o.x += p.x; o.y += p.y; o.z += p.z; o.w += p.w;
    }
    *(float4*)(out + i) = o;
}

// ---------------------------------------------------------------------------
// Launch: output layout = concat(out (B*OC*OF), adj (B*C*F*F)) in fp32.
// ---------------------------------------------------------------------------
extern "C" void kernel_launch(void* const* d_in, const int* in_sizes, int n_in,
                              void* d_out, int out_size)
{
    const float* x   = (const float*)d_in[0];
    const float* nb  = (const float*)d_in[1];
    const float* Wa1 = (const float*)d_in[2];
    const float* Wa2 = (const float*)d_in[3];
    const float* Wc  = (const float*)d_in[4];
    float* out = (float*)d_out;
    float* adj = out + (size_t)B_ * OC_ * OF_;

    static int attr_done = 0;
    if (!attr_done) {
        cudaFuncSetAttribute(k2_adj, cudaFuncAttributeMaxDynamicSharedMemorySize, K2_DSMEM);
        cudaFuncSetAttribute(k3_gemm, cudaFuncAttributeMaxDynamicSharedMemorySize, K3_DSMEM);
        attr_done = 1;
    }

    k1a_logits<<<B_ * 4, 256>>>(nb, Wa2);
    k1b_softmax<<<B_, 256>>>(x, Wa1);
    k2_adj<<<B_ * C_, 512, K2_DSMEM>>>(x, nb, adj);
    k3_gemm<<<dim3(16, 2, KSPLIT), 128, K3_DSMEM>>>(Wc);
    k4_reduce<<<512, 256>>>(out);
}

// round 9
// speedup vs baseline: 1.3426x; 1.3426x over previous
#include <cuda_runtime.h>
#include <cstdint>
#include <cstddef>

#define B_  256
#define C_  4
#define N_  64
#define F_  256
#define OC_ 8
#define OF_ 256
#define KSPLIT 8

typedef unsigned long long ull;

// Scratch (no allocations allowed)
__device__ float g_z[B_ * 2 * C_ * F_];            // 2 MB : concat(h, x)
__device__ float g_w[B_ * N_];                     // softmax weights
__device__ float g_s2[B_ * N_];                    // raw neighbor logits
__device__ float g_part[KSPLIT * B_ * OC_ * OF_];  // 16 MB : split-K partials

__device__ __forceinline__ float sqrt_ap(float v) {
    float r; asm("sqrt.approx.f32 %0, %1;" : "=f"(r) : "f"(v)); return r;
}
__device__ __forceinline__ float rcp_ap(float v) {
    float r; asm("rcp.approx.f32 %0, %1;" : "=f"(r) : "f"(v)); return r;
}
__device__ __forceinline__ ull pack2f(float v) {
    ull r; asm("mov.b64 %0, {%1, %2};" : "=l"(r) : "f"(v), "f"(v)); return r;
}
__device__ __forceinline__ void ffma2(ull& d, ull a, ull b) {
    asm("fma.rn.f32x2 %0, %1, %2, %0;" : "+l"(d) : "l"(a), "l"(b));
}

// ---------------------------------------------------------------------------
// Kernel 1a: s2 logits. Grid 1024.
// ---------------------------------------------------------------------------
__global__ __launch_bounds__(256) void k1a_logits(
    const float* __restrict__ nb, const float* __restrict__ Wa2)
{
    __shared__ float ws2[256];
    const int b = blockIdx.x >> 2, quarter = blockIdx.x & 3;
    const int t = threadIdx.x;
    const int lane = t & 31, w = t >> 5;

    ws2[t] = Wa2[t] + Wa2[256 + t] + Wa2[512 + t] + Wa2[768 + t];
    __syncthreads();

    const float* nbb = nb + (size_t)b * 65536;
    #pragma unroll
    for (int j = 0; j < 2; j++) {
        const int n = quarter * 16 + w * 2 + j;
        const float4* np = (const float4*)(nbb + n * 1024);
        float acc = 0.f;
        #pragma unroll
        for (int it = 0; it < 8; it++) {
            float4 q = np[it * 32 + lane];
            int f = (it * 128 + lane * 4) & 255;
            acc += q.x * ws2[f] + q.y * ws2[f + 1] + q.z * ws2[f + 2] + q.w * ws2[f + 3];
        }
        #pragma unroll
        for (int o = 16; o > 0; o >>= 1) acc += __shfl_xor_sync(0xffffffffu, acc, o);
        if (lane == 0) g_s2[b * 64 + n] = acc;
    }
}

// ---------------------------------------------------------------------------
// Kernel 1b: s1 + softmax; copy x into z channels 4..7.
// ---------------------------------------------------------------------------
__global__ __launch_bounds__(256) void k1b_softmax(
    const float* __restrict__ x, const float* __restrict__ Wa1)
{
    __shared__ float red[8];
    const int b = blockIdx.x;
    const int t = threadIdx.x;
    const int lane = t & 31, w = t >> 5;

    float w1 = Wa1[t] + Wa1[256 + t] + Wa1[512 + t] + Wa1[768 + t];

    float xs = 0.f;
    #pragma unroll
    for (int c = 0; c < 4; c++) {
        float xv = x[(b * 4 + c) * 256 + t];
        g_z[b * 2048 + (4 + c) * 256 + t] = xv;
        xs += xv;
    }
    float p = xs * w1;
    #pragma unroll
    for (int o = 16; o > 0; o >>= 1) p += __shfl_xor_sync(0xffffffffu, p, o);
    if (lane == 0) red[w] = p;
    __syncthreads();

    if (w == 0) {
        float s1v = red[lane & 7];
        #pragma unroll
        for (int o = 4; o > 0; o >>= 1) s1v += __shfl_xor_sync(0xffffffffu, s1v, o);
        float l0 = s1v * g_s2[b * 64 + lane];
        float l1 = s1v * g_s2[b * 64 + lane + 32];
        float m = fmaxf(l0, l1);
        #pragma unroll
        for (int o = 16; o > 0; o >>= 1) m = fmaxf(m, __shfl_xor_sync(0xffffffffu, m, o));
        float e0 = __expf(l0 - m), e1 = __expf(l1 - m);
        float s = e0 + e1;
        #pragma unroll
        for (int o = 16; o > 0; o >>= 1) s += __shfl_xor_sync(0xffffffffu, s, o);
        float inv = 1.f / s;
        g_w[b * 64 + lane]      = e0 * inv;
        g_w[b * 64 + lane + 32] = e1 * inv;
    }
}

// ---------------------------------------------------------------------------
// Kernel 2: v + adj + fused h. REVERTED to the round-7 version (measured in
// the 172us run): 256 thr, static smem, recompute-sqrt, 6 blocks/SM. The
// round-8 smem-a-tile variant dropped to 1 block/SM and regressed ~50us.
// ---------------------------------------------------------------------------
__global__ __launch_bounds__(256) void k2_adj(
    const float* __restrict__ x, const float* __restrict__ nb,
    float* __restrict__ adj)
{
    __shared__ float xs[256], vs[256], us[256], idn[256];
    __shared__ float wsm[64];
    __shared__ float pden[4 * 256];

    const int bc = blockIdx.x;
    const int b = bc >> 2, c = bc & 3;
    const int t = threadIdx.x;

    if (t < 64) wsm[t] = g_w[b * 64 + t];
    xs[t] = x[bc * 256 + t];
    __syncthreads();

    {
        const float* nbp = nb + ((size_t)b * 256 + c) * 256 + t;
        float acc = 0.f;
        #pragma unroll 8
        for (int n = 0; n < 64; n++) acc += wsm[n] * nbp[(size_t)n * 1024];
        vs[t] = acc;
    }
    __syncthreads();

    const int r = t >> 6, cg = t & 63;
    const int i0 = r * 64;
    float xc[4], vc[4];
    #pragma unroll
    for (int j = 0; j < 4; j++) { xc[j] = xs[4 * cg + j]; vc[j] = vs[4 * cg + j]; }

    float d[4] = {0.f, 0.f, 0.f, 0.f};
    #pragma unroll 4
    for (int ii = 0; ii < 64; ii++) {
        const int i = i0 + ii;
        const float xi = xs[i], vi = vs[i];
        #pragma unroll
        for (int j = 0; j < 4; j++) {
            float tv = xi * vc[j] + xc[j] * vi;
            float s = sqrt_ap(fmaxf(fabsf(tv), 1e-8f));
            d[j] += (tv != 0.f) ? s : 0.f;
        }
    }
    #pragma unroll
    for (int j = 0; j < 4; j++) pden[r * 256 + 4 * cg + j] = d[j];
    __syncthreads();

    {
        float den = pden[t] + pden[256 + t] + pden[512 + t] + pden[768 + t];
        float id = rcp_ap(den + 1e-7f);
        idn[t] = id;
        us[t] = xs[t] * id;
    }
    __syncthreads();

    float ic[4];
    #pragma unroll
    for (int j = 0; j < 4; j++) ic[j] = idn[4 * cg + j];
    float h[4] = {0.f, 0.f, 0.f, 0.f};
    float* ap = adj + (size_t)bc * 65536 + 4 * cg;

    #pragma unroll 4
    for (int ii = 0; ii < 64; ii++) {
        const int i = i0 + ii;
        const float xi = xs[i], vi = vs[i], usi = us[i];
        float4 o;
        #pragma unroll
        for (int j = 0; j < 4; j++) {
            float tv = xi * vc[j] + xc[j] * vi;
            float s = sqrt_ap(fmaxf(fabsf(tv), 1e-8f));
            float a = (tv != 0.f) ? copysignf(s, tv) : 0.f;
            (&o.x)[j] = a * ic[j];
            h[j] = fmaf(a, usi, h[j]);
        }
        __stcs((float4*)(ap + (size_t)i * 256), o);
    }
    #pragma unroll
    for (int j = 0; j < 4; j++) pden[r * 256 + 4 * cg + j] = h[j];
    __syncthreads();

    float hs = pden[t] + pden[256 + t] + pden[512 + t] + pden[768 + t];
    g_z[b * 2048 + c * 256 + t] = hs;
}

// ---------------------------------------------------------------------------
// Kernel 3: split-K GEMM (round-8 version, kept: 84.5 -> 73.2us win).
// grid (16,2,8), 128 thr, tile 128x128, per-thread m16 x n8, dup-B.
// ---------------------------------------------------------------------------
#define K3_BROW 288
#define K3_DSMEM ((2 * 16 * 128 + 2 * 16 * K3_BROW) * 4)   // 53248 B

__global__ __launch_bounds__(128) void k3_gemm(const float* __restrict__ W)
{
    extern __shared__ float sm3[];
    float* const Asb = sm3;                   // 2 x [16][128]
    float* const Bdb = sm3 + 2 * 16 * 128;    // 2 x [16][K3_BROW]

    const int t = threadIdx.x;
    const int bn = blockIdx.x * 128, bm = blockIdx.y * 128, ks = blockIdx.z;
    const int mt = t >> 4;                           // 0..7
    const int nt = t & 15;                           // 0..15
    const int aoff = mt * 16;
    const int boff = nt * 16 + (nt >> 1) * 4;
    const int gn = t >> 3;
    const int bso = gn * 16 + (gn >> 1) * 4 + (t & 7) * 2;

    const float* Ag = g_z + (size_t)(bm + t) * 2048 + ks * 256;
    const float* Bg = W + (size_t)(bn + t) * 2048 + ks * 256;

    float4 apf[4], bpf[4];
    #pragma unroll
    for (int i = 0; i < 4; i++) { apf[i] = *(const float4*)(Ag + 4 * i); bpf[i] = *(const float4*)(Bg + 4 * i); }

    ull acc[8][8];
    #pragma unroll
    for (int mp = 0; mp < 8; mp++)
        #pragma unroll
        for (int n = 0; n < 8; n++) acc[mp][n] = 0ull;

    int buf = 0;
    for (int ch = 0; ch < 16; ch++) {
        float* As = Asb + buf * 2048;
        float* Bd = Bdb + buf * 16 * K3_BROW;
        #pragma unroll
        for (int i = 0; i < 4; i++)
            #pragma unroll
            for (int j = 0; j < 4; j++) {
                As[(i * 4 + j) * 128 + t] = (&apf[i].x)[j];
                *(ull*)&Bd[(i * 4 + j) * K3_BROW + bso] = pack2f((&bpf[i].x)[j]);
            }
        __syncthreads();

        if (ch < 15) {
            const float* Ag2 = Ag + (ch + 1) * 16;
            const float* Bg2 = Bg + (ch + 1) * 16;
            #pragma unroll
            for (int i = 0; i < 4; i++) { apf[i] = *(const float4*)(Ag2 + 4 * i); bpf[i] = *(const float4*)(Bg2 + 4 * i); }
        }

        #pragma unroll 4
        for (int k = 0; k < 16; k++) {
            const ull* ar = (const ull*)&As[k * 128 + aoff];
            const ull* br = (const ull*)&Bd[k * K3_BROW + boff];
            ull a[8], bb[8];
            #pragma unroll
            for (int i = 0; i < 8; i++) { a[i] = ar[i]; bb[i] = br[i]; }
            #pragma unroll
            for (int mp = 0; mp < 8; mp++)
                #pragma unroll
                for (int n = 0; n < 8; n++)
                    ffma2(acc[mp][n], a[mp], bb[n]);
        }
        buf ^= 1;
        __syncthreads();
    }

    // store split-K partials: acc[mp][n] = (row 2mp, row 2mp+1)
    float* pp = g_part + (size_t)ks * 524288;
    #pragma unroll
    for (int mp = 0; mp < 8; mp++) {
        const int r0 = bm + mt * 16 + 2 * mp;
        float lo[8], hi[8];
        #pragma unroll
        for (int n = 0; n < 8; n++) {
            float2 v = *(float2*)&acc[mp][n];
            lo[n] = v.x; hi[n] = v.y;
        }
        float* p0 = pp + (size_t)r0 * 2048 + bn + nt * 8;
        *(float4*)p0       = make_float4(lo[0], lo[1], lo[2], lo[3]);
        *(float4*)(p0 + 4) = make_float4(lo[4], lo[5], lo[6], lo[7]);
        float* p1 = p0 + 2048;
        *(float4*)p1       = make_float4(hi[0], hi[1], hi[2], hi[3]);
        *(float4*)(p1 + 4) = make_float4(hi[4], hi[5], hi[6], hi[7]);
    }
}

// ---------------------------------------------------------------------------
// Kernel 4: sum 8 split-K partials into out.
// ---------------------------------------------------------------------------
__global__ __launch_bounds__(256) void k4_reduce(float* __restrict__ out)
{
    const int i = (blockIdx.x * 256 + threadIdx.x) * 4;
    float4 o = *(const float4*)(g_part + i);
    #pragma unroll
    for (int s = 1; s < KSPLIT; s++) {
        const float4 p = *(const float4*)(g_part + (size_t)s * 524288 + i);
        o.x += p.x; o.y += p.y; o.z += p.z; o.w += p.w;
    }
    *(float4*)(out + i) = o;
}

// ---------------------------------------------------------------------------
// Launch: output layout = concat(out (B*OC*OF), adj (B*C*F*F)) in fp32.
// ---------------------------------------------------------------------------
extern "C" void kernel_launch(void* const* d_in, const int* in_sizes, int n_in,
                              void* d_out, int out_size)
{
    const float* x   = (const float*)d_in[0];
    const float* nb  = (const float*)d_in[1];
    const float* Wa1 = (const float*)d_in[2];
    const float* Wa2 = (const float*)d_in[3];
    const float* Wc  = (const float*)d_in[4];
    float* out = (float*)d_out;
    float* adj = out + (size_t)B_ * OC_ * OF_;

    static int attr_done = 0;
    if (!attr_done) {
        cudaFuncSetAttribute(k3_gemm, cudaFuncAttributeMaxDynamicSharedMemorySize, K3_DSMEM);
        attr_done = 1;
    }

    k1a_logits<<<B_ * 4, 256>>>(nb, Wa2);
    k1b_softmax<<<B_, 256>>>(x, Wa1);
    k2_adj<<<B_ * C_, 256>>>(x, nb, adj);
    k3_gemm<<<dim3(16, 2, KSPLIT), 128, K3_DSMEM>>>(Wc);
    k4_reduce<<<512, 256>>>(out);
}